// round 14
// baseline (speedup 1.0000x reference)
#include <cuda_runtime.h>

#define BB 64
#define TT 512
#define DD 1024
#define NBLK 128
#define EPSV 1e-6f

typedef unsigned long long u64;

// packed fp32x2 FMA: c = a*b + c (elementwise, exact IEEE fp32 per lane)
#define FMA2(c, a, b) \
    asm("fma.rn.f32x2 %0, %1, %2, %3;" : "=l"(c) : "l"(a), "l"(b), "l"(c))

__device__ __forceinline__ u64 pack2(float x) {
    u64 r;
    asm("mov.b64 %0, {%1, %1};" : "=l"(r) : "r"(__float_as_uint(x)));
    return r;
}
__device__ __forceinline__ float2 unpack2(u64 v) {
    float2 f;
    asm("mov.b64 {%0, %1}, %2;" : "=f"(f.x), "=f"(f.y) : "l"(v));
    return f;
}

// ---------------- device scratch (no allocations allowed) ----------------
__device__ float g_xtau[(size_t)BB * TT * DD];     // 134 MB
__device__ float g_mem [(size_t)BB * TT * DD];     // 134 MB
__device__ float g_tauT[DD * BB];                  // tau transposed: tauT[e*64+b]
__device__ float g_partial[8 * BB * DD];           // split-K partials [kc][b][e]
// distributed barrier flags: one per block, 128B apart (distinct LTS slices).
// NEVER reset — monotonic across graph replays; each launch derives its base
// from its own flag (all flags equal at every launch boundary).
__device__ unsigned int g_flags[NBLK * 32];

// ---------------- big GEMM: out[m][e] = sum_k x[m][k]*W[k][e] + bias[e] ----------------
// M=32768, N=1024, K=1024. z=0 -> (W_tau[:D], b_tau, g_xtau), z=1 -> (W_mem, b_mem, g_mem)
// Double-buffered smem pipeline: 1 __syncthreads per k-tile, LDG overlapped with FMA.
__global__ void __launch_bounds__(256) gemm_kernel(
    const float* __restrict__ x,
    const float* __restrict__ Wt, const float* __restrict__ bt,
    const float* __restrict__ Wm, const float* __restrict__ bm)
{
    const float* W;
    const float* bias;
    float* out;
    if (blockIdx.z == 0) { W = Wt; bias = bt; out = g_xtau; }
    else                 { W = Wm; bias = bm; out = g_mem;  }

    __shared__ __align__(16) float As[2][16][68];   // [buf][k][m] padded
    __shared__ __align__(16) float Bs[2][16][64];   // [buf][k][n]

    const int tid = threadIdx.x;
    const int tx = tid & 15;        // n direction
    const int ty = tid >> 4;        // m direction
    const int m0 = blockIdx.y * 64;
    const int n0 = blockIdx.x * 64;

    const int ar  = tid >> 2;        // A row 0..63
    const int ac4 = tid & 3;         // A float4 index within 16 k
    const int br  = tid >> 4;        // B k-row 0..15
    const int bc4 = tid & 15;        // B float4 index 0..15

    const float* a_src = &x[(size_t)(m0 + ar) * 1024 + ac4 * 4];
    const float* b_src = &W[(size_t)br * 1024 + n0 + bc4 * 4];

    // prologue: load tile 0 into buffer 0
    {
        float4 a = *(const float4*)a_src;
        As[0][ac4 * 4 + 0][ar] = a.x;
        As[0][ac4 * 4 + 1][ar] = a.y;
        As[0][ac4 * 4 + 2][ar] = a.z;
        As[0][ac4 * 4 + 3][ar] = a.w;
        *(float4*)&Bs[0][br][bc4 * 4] = *(const float4*)b_src;
    }
    __syncthreads();

    u64 acc[2][4] = {};

    for (int k0 = 0; k0 < 1024; k0 += 16) {
        const int cur = (k0 >> 4) & 1;
        const bool has_next = (k0 + 16) < 1024;

        float4 a_n, b_n;
        if (has_next) {
            a_n = *(const float4*)(a_src + k0 + 16);
            b_n = *(const float4*)(b_src + (size_t)(k0 + 16) * 1024);
        }

#pragma unroll
        for (int kk = 0; kk < 16; kk++) {
            ulonglong2 a = *(const ulonglong2*)&As[cur][kk][ty * 4];   // 2 m-pairs
            float4 b = *(const float4*)&Bs[cur][kk][tx * 4];
            u64 b0 = pack2(b.x), b1 = pack2(b.y), b2 = pack2(b.z), b3 = pack2(b.w);
            FMA2(acc[0][0], a.x, b0); FMA2(acc[0][1], a.x, b1);
            FMA2(acc[0][2], a.x, b2); FMA2(acc[0][3], a.x, b3);
            FMA2(acc[1][0], a.y, b0); FMA2(acc[1][1], a.y, b1);
            FMA2(acc[1][2], a.y, b2); FMA2(acc[1][3], a.y, b3);
        }

        if (has_next) {
            const int nxt = cur ^ 1;
            As[nxt][ac4 * 4 + 0][ar] = a_n.x;
            As[nxt][ac4 * 4 + 1][ar] = a_n.y;
            As[nxt][ac4 * 4 + 2][ar] = a_n.z;
            As[nxt][ac4 * 4 + 3][ar] = a_n.w;
            *(float4*)&Bs[nxt][br][bc4 * 4] = b_n;
            __syncthreads();
        }
    }

    float4 bb = *(const float4*)&bias[n0 + tx * 4];
#pragma unroll
    for (int p = 0; p < 2; p++) {
        float2 c0 = unpack2(acc[p][0]);
        float2 c1 = unpack2(acc[p][1]);
        float2 c2 = unpack2(acc[p][2]);
        float2 c3 = unpack2(acc[p][3]);
        int r = m0 + ty * 4 + 2 * p;
        float4 o0 = make_float4(c0.x + bb.x, c1.x + bb.y, c2.x + bb.z, c3.x + bb.w);
        float4 o1 = make_float4(c0.y + bb.x, c1.y + bb.y, c2.y + bb.z, c3.y + bb.w);
        *(float4*)&out[(size_t)r * 1024 + n0 + tx * 4] = o0;
        *(float4*)&out[(size_t)(r + 1) * 1024 + n0 + tx * 4] = o1;
    }
}

// ---------------- distributed-flag grid barrier ----------------
// Arrival: 1 release-store to this block's own flag (no contention).
// Wait: threads 0..127 each poll ONE distinct flag (parallel, no serialization).
__device__ __forceinline__ void gridbar(unsigned int target)
{
    __syncthreads();   // all threads of block done with previous phase
    if (threadIdx.x == 0) {
        asm volatile("st.release.gpu.global.u32 [%0], %1;"
                     :: "l"(&g_flags[blockIdx.x * 32]), "r"(target) : "memory");
    }
    if (threadIdx.x < NBLK) {
        unsigned int v;
        do {
            asm volatile("ld.acquire.gpu.global.u32 %0, [%1];"
                         : "=r"(v) : "l"(&g_flags[threadIdx.x * 32]) : "memory");
        } while ((int)(v - target) < 0);
    }
    __syncthreads();
}

// ---------------- persistent recurrence kernel ----------------
__global__ void __launch_bounds__(256) recur_kernel(
    const float* __restrict__ Wtau,
    const float* __restrict__ log_thresh,
    float* __restrict__ out)
{
    extern __shared__ float sm[];
    float (*Ws)[64] = (float(*)[64])sm;              // [128][64] persistent W_tt chunk
    float (*ts)[64] = (float(*)[64])(sm + 128 * 64); // [128][64] tau chunk (tauT layout)

    const int tid = threadIdx.x;
    const int bid = blockIdx.x;
    const int nc = bid & 15;
    const int kc = bid >> 4;
    const int tx = tid & 15;   // e direction
    const int ty = tid >> 4;   // b direction

    const float* Wtt = Wtau + (size_t)DD * DD;

    // barrier base: all flags are equal at every launch boundary (monotonic scheme)
    unsigned int bar_cnt;
    asm volatile("ld.acquire.gpu.global.u32 %0, [%1];"
                 : "=r"(bar_cnt) : "l"(&g_flags[bid * 32]) : "memory");

    // Load persistent W_tt chunk: k in [kc*128,+128), e in [nc*64,+64)
#pragma unroll
    for (int i = 0; i < 8; i++) {
        int idx4 = tid + i * 256;
        int k = idx4 >> 4;
        int c = idx4 & 15;
        *(float4*)&Ws[k][c * 4] =
            *(const float4*)&Wtt[(size_t)(kc * 128 + k) * 1024 + nc * 64 + c * 4];
    }

    // tau0 = 1.0
    {
        int base = bid * 512;
        g_tauT[base + tid] = 1.0f;
        g_tauT[base + 256 + tid] = 1.0f;
    }

    // Static per-thread phase-2 ownership (2 outputs)
    const int oi0 = tid, oi1 = tid + 256;
    const int b0 = kc * 8 + (oi0 >> 6), e0 = nc * 64 + (oi0 & 63);
    const int b1 = kc * 8 + (oi1 >> 6), e1 = nc * 64 + (oi1 & 63);
    float v0 = 0.f, v1 = 0.f;
    const float th0 = 1.f / (1.f + expf(-log_thresh[e0]));
    const float th1 = 1.f / (1.f + expf(-log_thresh[e1]));

    float* out_tau = out + (size_t)BB * TT * DD;
    float* out_v   = out_tau + BB * DD;
    float* out_th  = out_v + BB * DD;

    __threadfence();
    gridbar(++bar_cnt);   // tau0 init visible everywhere

#pragma unroll 1
    for (int t = 0; t < TT; t++) {
        // Prefetch phase-2 operands (constant data; latency hides under phase 1)
        const size_t i0 = (size_t)(b0 * TT + t) * DD + e0;
        const size_t i1 = (size_t)(b1 * TT + t) * DD + e1;
        float pf_xt0 = __ldg((const float*)&g_xtau[i0]);
        float pf_mm0 = __ldg((const float*)&g_mem[i0]);
        float pf_xt1 = __ldg((const float*)&g_xtau[i1]);
        float pf_mm1 = __ldg((const float*)&g_mem[i1]);

        // ---- phase 1: load tau chunk, partial GEMM with f32x2
#pragma unroll
        for (int i = 0; i < 8; i++) {
            int idx4 = tid + i * 256;
            float4 v4 = __ldcg((const float4*)&g_tauT[kc * 128 * 64 + idx4 * 4]);
            *(float4*)&((float*)ts)[idx4 * 4] = v4;
        }
        __syncthreads();

        u64 acc[2][4] = {};
#pragma unroll 4
        for (int kk = 0; kk < 128; kk++) {
            ulonglong2 a = *(const ulonglong2*)&ts[kk][ty * 4];   // 2 b-pairs
            float4 w = *(const float4*)&Ws[kk][tx * 4];
            u64 w0 = pack2(w.x), w1 = pack2(w.y), w2 = pack2(w.z), w3 = pack2(w.w);
            FMA2(acc[0][0], a.x, w0); FMA2(acc[0][1], a.x, w1);
            FMA2(acc[0][2], a.x, w2); FMA2(acc[0][3], a.x, w3);
            FMA2(acc[1][0], a.y, w0); FMA2(acc[1][1], a.y, w1);
            FMA2(acc[1][2], a.y, w2); FMA2(acc[1][3], a.y, w3);
        }
#pragma unroll
        for (int p = 0; p < 2; p++) {
            float2 c0 = unpack2(acc[p][0]);
            float2 c1 = unpack2(acc[p][1]);
            float2 c2 = unpack2(acc[p][2]);
            float2 c3 = unpack2(acc[p][3]);
            int b = ty * 4 + 2 * p;
            *(float4*)&g_partial[(size_t)(kc * 64 + b) * 1024 + nc * 64 + tx * 4] =
                make_float4(c0.x, c1.x, c2.x, c3.x);
            *(float4*)&g_partial[(size_t)(kc * 64 + b + 1) * 1024 + nc * 64 + tx * 4] =
                make_float4(c0.y, c1.y, c2.y, c3.y);
        }

        __threadfence();
        gridbar(++bar_cnt);   // all partials visible

        // ---- phase 2: finalize 2 owned (b,e) outputs
        {
            float sum = pf_xt0;
#pragma unroll
            for (int p = 0; p < 8; p++)
                sum += __ldcg(&g_partial[(size_t)(p * 64 + b0) * 1024 + e0]);
            float tau = 1.f / (1.f + expf(-sum));
            float alpha = expf(-1.f / (tau + EPSV));
            v0 = alpha * v0 + (1.f - alpha) * pf_mm0;
            float s = (v0 >= th0) ? 1.f : 0.f;
            v0 = v0 * (1.f - s);
            out[i0] = s;
            g_tauT[e0 * 64 + b0] = tau;
            if (t == TT - 1) {
                out_tau[b0 * DD + e0] = tau;
                out_v[b0 * DD + e0] = v0;
                if (b0 == 0) out_th[e0] = th0;
            }
        }
        {
            float sum = pf_xt1;
#pragma unroll
            for (int p = 0; p < 8; p++)
                sum += __ldcg(&g_partial[(size_t)(p * 64 + b1) * 1024 + e1]);
            float tau = 1.f / (1.f + expf(-sum));
            float alpha = expf(-1.f / (tau + EPSV));
            v1 = alpha * v1 + (1.f - alpha) * pf_mm1;
            float s = (v1 >= th1) ? 1.f : 0.f;
            v1 = v1 * (1.f - s);
            out[i1] = s;
            g_tauT[e1 * 64 + b1] = tau;
            if (t == TT - 1) {
                out_tau[b1 * DD + e1] = tau;
                out_v[b1 * DD + e1] = v1;
                if (b1 == 0) out_th[e1] = th1;
            }
        }

        __threadfence();
        gridbar(++bar_cnt);   // new tauT visible before next step's phase 1
    }
}

// ---------------- launcher ----------------
extern "C" void kernel_launch(void* const* d_in, const int* in_sizes, int n_in,
                              void* d_out, int out_size)
{
    const float* x    = (const float*)d_in[0];
    const float* Wtau = (const float*)d_in[1];
    const float* btau = (const float*)d_in[2];
    const float* Wmem = (const float*)d_in[3];
    const float* bmem = (const float*)d_in[4];
    const float* lth  = (const float*)d_in[5];
    float* out = (float*)d_out;

    (void)in_sizes; (void)n_in; (void)out_size;

    cudaFuncSetAttribute(recur_kernel,
                         cudaFuncAttributeMaxDynamicSharedMemorySize, 65536);

    dim3 g1(16, 512, 2);
    gemm_kernel<<<g1, 256>>>(x, Wtau, btau, Wmem, bmem);

    recur_kernel<<<NBLK, 256, 65536>>>(Wtau, lth, out);
}